// round 6
// baseline (speedup 1.0000x reference)
#include <cuda_runtime.h>
#include <cuda_fp16.h>
#include <cstdint>

// ---------------------------------------------------------------------------
// PatchNCELoss B=8192 D=128 T=0.07 via mma.sync m16n8k16 fp16 (HMMA).
// loss[b] = 1/T + log(sum_k exp((S[b,k]-1)/T)) - pos[b]/T
// A pre-scaled by log2(e)/T; accumulators init at -log2(e)/T -> epilogue is
// pure ex2+add. Occupancy-2 (80KB smem, <=128 regs), 3-stage 64-key B ring,
// per-mi epilogue so tensor pipe is fed by the co-resident CTA.
// ---------------------------------------------------------------------------

#define BN  8192
#define BN2 8320              // 65 * 128
#define DD  128
#define KS  4                 // key splits
#define NKEY 64
#define NC  32                // 64-key chunks per CTA (8192/64/KS)
#define GRID_X 65

#define INV_T    14.285714285714286f
#define SCALE_L2 20.609929155556620f   /* log2(e)/T */

static __device__ __half g_Ap[BN2 * DD];   // fragment-permuted A * SCALE_L2
static __device__ __half g_Bv[BN * DD];    // fragment-permuted v_n keys
static __device__ __half g_Bi[BN * DD];    // fragment-permuted i_n keys
static __device__ float  g_posT[BN2];
static __device__ int    g_orig[BN2];
static __device__ int    g_cnt[2];
static __device__ float  g_partial[KS * BN2];

// smem: A 32KB | B ring 3 x 16KB
#define SMEM_TOT 81920

// ---------------------------------------------------------------------------
__device__ __forceinline__ float ex2f(float x) {
    float r; asm("ex2.approx.f32 %0,%1;" : "=f"(r) : "f"(x)); return r;
}
__device__ __forceinline__ uint32_t s2u(const void* p) {
    uint32_t a;
    asm("{ .reg .u64 t; cvta.to.shared.u64 t, %1; cvt.u32.u64 %0, t; }"
        : "=r"(a) : "l"(p));
    return a;
}
#define CPA16(dst, src) \
    asm volatile("cp.async.cg.shared.global [%0], [%1], 16;" :: "r"(dst), "l"(src))
#define CP_COMMIT() asm volatile("cp.async.commit_group;" ::: "memory")
#define CP_WAIT1()  asm volatile("cp.async.wait_group 1;" ::: "memory")

#define LDS128(r, a) \
    asm volatile("ld.shared.v4.b32 {%0,%1,%2,%3}, [%4];" \
        : "=r"((r)[0]), "=r"((r)[1]), "=r"((r)[2]), "=r"((r)[3]) : "r"(a))
#define LDS64(r, a) \
    asm volatile("ld.shared.v2.b32 {%0,%1}, [%2];" \
        : "=r"((r)[0]), "=r"((r)[1]) : "r"(a))

__device__ __forceinline__ void mma16816(float* c, const uint32_t* a,
                                         const uint32_t* b) {
    asm volatile(
        "mma.sync.aligned.m16n8k16.row.col.f32.f16.f16.f32 "
        "{%0,%1,%2,%3}, {%4,%5,%6,%7}, {%8,%9}, {%0,%1,%2,%3};"
        : "+f"(c[0]), "+f"(c[1]), "+f"(c[2]), "+f"(c[3])
        : "r"(a[0]), "r"(a[1]), "r"(a[2]), "r"(a[3]), "r"(b[0]), "r"(b[1]));
}

// fragment-permuted half index helpers
__device__ __forceinline__ int a_perm_idx(int s, int t) {
    int mb = s >> 4, q = s & 15, g = q & 7, hi = q >> 3;
    int kk = t >> 4, tc = t & 15, kh = tc >> 3, t4 = (tc >> 1) & 3, h = tc & 1;
    int lane = g * 4 + t4, r = hi + 2 * kh;
    return (((mb * 8 + kk) * 32 + lane) << 3) + r * 2 + h;
}
__device__ __forceinline__ int b_perm_idx(int b, int t) {
    int nb = b >> 3, g = b & 7;
    int kk = t >> 4, tc = t & 15, kh = tc >> 3, t4 = (tc >> 1) & 3, h = tc & 1;
    int lane = g * 4 + t4;
    return (((nb * 8 + kk) * 32 + lane) << 2) + kh * 2 + h;
}

// ---------------------------------------------------------------------------
__global__ void init_kernel() {
    if (threadIdx.x == 0) { g_cnt[0] = 0; g_cnt[1] = 0; }
}

__global__ void prep_kernel(const float* __restrict__ fv,
                            const float* __restrict__ fi,
                            const float* __restrict__ v,
                            const float* __restrict__ vi) {
    int b = blockIdx.x;
    int t = threadIdx.x;
    float xfv = fv[b * DD + t];
    float xfi = fi[b * DD + t];
    float xv  = v [b * DD + t];
    float xi  = vi[b * DD + t];

    float s[6];
    s[0] = xfv * xfv; s[1] = xfi * xfi; s[2] = xv * xv;
    s[3] = xi * xi;   s[4] = xfv * xv;  s[5] = xfi * xi;
#pragma unroll
    for (int off = 16; off; off >>= 1)
#pragma unroll
        for (int k = 0; k < 6; ++k)
            s[k] += __shfl_xor_sync(0xffffffffu, s[k], off);

    __shared__ float sh[4][6];
    __shared__ float bc[3];
    __shared__ int   bsl[2];
    int w = t >> 5, lane = t & 31;
    if (lane == 0)
#pragma unroll
        for (int k = 0; k < 6; ++k) sh[w][k] = s[k];
    __syncthreads();

    if (t == 0) {
        float tot[6];
#pragma unroll
        for (int k = 0; k < 6; ++k)
            tot[k] = sh[0][k] + sh[1][k] + sh[2][k] + sh[3][k];
        float inv_fv = 1.f / fmaxf(sqrtf(tot[0]), 1e-12f);
        float inv_fi = 1.f / fmaxf(sqrtf(tot[1]), 1e-12f);
        float inv_v  = 1.f / fmaxf(sqrtf(tot[2]), 1e-12f);
        float inv_i  = 1.f / fmaxf(sqrtf(tot[3]), 1e-12f);
        float pos_v = tot[4] * inv_fv * inv_v;
        float pos_i = tot[5] * inv_fi * inv_i;
        bool use_v = (pos_v >= pos_i);
        int slot = use_v ? atomicAdd(&g_cnt[0], 1)
                         : (BN2 - 1 - atomicAdd(&g_cnt[1], 1));
        g_orig[slot] = b;
        g_posT[slot] = (use_v ? pos_v : pos_i) * INV_T;
        bc[0] = inv_v; bc[1] = inv_i; bc[2] = use_v ? inv_fv : inv_fi;
        bsl[0] = slot; bsl[1] = use_v ? 1 : 0;
    }
    __syncthreads();

    g_Bv[b_perm_idx(b, t)] = __float2half_rn(xv * bc[0]);
    g_Bi[b_perm_idx(b, t)] = __float2half_rn(xi * bc[1]);
    g_Ap[a_perm_idx(bsl[0], t)] =
        __float2half_rn((bsl[1] ? xfv : xfi) * bc[2] * SCALE_L2);
}

__global__ void zero_pad_kernel() {
    int row = g_cnt[0] + blockIdx.x;
    int t = threadIdx.x;
    g_Ap[a_perm_idx(row, t)] = __float2half_rn(0.f);
    if (t == 0) g_orig[row] = -1;
}

// ---------------------------------------------------------------------------
__global__ __launch_bounds__(256, 2) void gemm_lse_kernel() {
    extern __shared__ __align__(16) unsigned char sm[];
    __shared__ float red[128][4];

    const uint32_t smA = s2u(sm);

    const int tid  = threadIdx.x;
    const int lane = tid & 31;
    const int wid  = tid >> 5;
    const int wm = wid >> 2;          // 0..1  (64-row block)
    const int wn = wid & 3;           // 0..3  (16-key block)

    const int c0 = g_cnt[0];
    const int bx = blockIdx.x, ks = blockIdx.y;
    const int grp = (bx > (c0 >> 7)) ? 1 : 0;
    const int row0 = bx << 7;
    const char* __restrict__ Kb = (const char*)(grp ? g_Bi : g_Bv);

    // prologue: A + B0 (group 0), B1 (group 1)
    {
        const char* Asrc = (const char*)g_Ap + (size_t)row0 * 256;
#pragma unroll
        for (int q = 0; q < 8; ++q) {
            int i = (tid + q * 256) * 16;
            CPA16(smA + (uint32_t)i, Asrc + i);
        }
        const char* Bsrc = Kb + (size_t)ks * 16384;
#pragma unroll
        for (int q = 0; q < 4; ++q) {
            int i = (tid + q * 256) * 16;
            CPA16(smA + 32768u + (uint32_t)i, Bsrc + i);
        }
        CP_COMMIT();
        Bsrc = Kb + (size_t)(ks + KS) * 16384;
#pragma unroll
        for (int q = 0; q < 4; ++q) {
            int i = (tid + q * 256) * 16;
            CPA16(smA + 49152u + (uint32_t)i, Bsrc + i);
        }
        CP_COMMIT();
    }

    float rsum[8];
#pragma unroll
    for (int i = 0; i < 8; ++i) rsum[i] = 0.f;

    const uint32_t aoff = smA + (uint32_t)(wm * 16384 + lane * 16);
    const uint32_t boff = (uint32_t)(wn * 4096 + lane * 8);

    // B ring registers: cur = buf(ci), nxt = buf(ci+1), pf = buf(ci+2) target
    uint32_t b_cur = smA + 32768u, b_nxt = smA + 49152u, b_pf = smA + 65536u;

#pragma unroll 1
    for (int ci = 0; ci < NC; ++ci) {
        CP_WAIT1();               // B(ci) resident
        __syncthreads();          // all warps done with buf now being refilled

        if (ci + 2 < NC) {
            const char* Bs = Kb + (size_t)(ks + (ci + 2) * KS) * 16384;
#pragma unroll
            for (int q = 0; q < 4; ++q) {
                int i = (tid + q * 256) * 16;
                CPA16(b_pf + (uint32_t)i, Bs + i);
            }
        }
        CP_COMMIT();

        const uint32_t sB = b_cur + boff;
#pragma unroll
        for (int mi = 0; mi < 4; ++mi) {
            float c[2][4];
#pragma unroll
            for (int ni = 0; ni < 2; ++ni)
#pragma unroll
                for (int x = 0; x < 4; ++x) c[ni][x] = -SCALE_L2;

#pragma unroll
            for (int kk = 0; kk < 8; ++kk) {
                uint32_t a[4], b[2][2];
                LDS128(a, aoff + (uint32_t)(mi * 4096 + kk * 512));
                LDS64(b[0], sB + (uint32_t)(kk * 256));
                LDS64(b[1], sB + (uint32_t)(2048 + kk * 256));
                mma16816(c[0], a, b[0]);
                mma16816(c[1], a, b[1]);
            }
            rsum[mi * 2]     += ex2f(c[0][0]) + ex2f(c[0][1]) +
                                ex2f(c[1][0]) + ex2f(c[1][1]);
            rsum[mi * 2 + 1] += ex2f(c[0][2]) + ex2f(c[0][3]) +
                                ex2f(c[1][2]) + ex2f(c[1][3]);
        }

        // rotate ring
        uint32_t t0 = b_cur; b_cur = b_nxt; b_nxt = b_pf; b_pf = t0;
    }

    // reduce across the 4 col-lanes of each row
#pragma unroll
    for (int mi = 0; mi < 4; ++mi)
#pragma unroll
        for (int h = 0; h < 2; ++h) {
            float val = rsum[mi * 2 + h];
            val += __shfl_xor_sync(0xffffffffu, val, 1);
            val += __shfl_xor_sync(0xffffffffu, val, 2);
            if ((lane & 3) == 0)
                red[wm * 64 + mi * 16 + h * 8 + (lane >> 2)][wn] = val;
        }
    __syncthreads();

    if (tid < 128) {
        int slot = row0 + tid;
        float sum = red[tid][0] + red[tid][1] + red[tid][2] + red[tid][3];
        g_partial[ks * BN2 + slot] = sum;
    }
}

// ---------------------------------------------------------------------------
__global__ void finalize_kernel(float* __restrict__ out) {
    int s = blockIdx.x * 256 + threadIdx.x;
    if (s < BN2) {
        int o = g_orig[s];
        if (o >= 0) {
            float sum = g_partial[s] + g_partial[BN2 + s] +
                        g_partial[2 * BN2 + s] + g_partial[3 * BN2 + s];
            out[o] = INV_T + logf(sum) - g_posT[s];
        }
    }
}

// ---------------------------------------------------------------------------
extern "C" void kernel_launch(void* const* d_in, const int* in_sizes, int n_in,
                              void* d_out, int out_size) {
    (void)in_sizes; (void)n_in; (void)out_size;
    const float* fv = (const float*)d_in[0];
    const float* fi = (const float*)d_in[1];
    const float* v  = (const float*)d_in[2];
    const float* vi = (const float*)d_in[3];
    float* out = (float*)d_out;

    cudaFuncSetAttribute(gemm_lse_kernel,
                         cudaFuncAttributeMaxDynamicSharedMemorySize, SMEM_TOT);

    init_kernel<<<1, 32>>>();
    prep_kernel<<<BN, 128>>>(fv, fi, v, vi);
    zero_pad_kernel<<<128, 128>>>();
    gemm_lse_kernel<<<dim3(GRID_X, KS), 256, SMEM_TOT>>>();
    finalize_kernel<<<(BN2 + 255) / 256, 256>>>(out);
}

// round 7
// speedup vs baseline: 1.0153x; 1.0153x over previous
#include <cuda_runtime.h>
#include <cuda_fp16.h>
#include <cstdint>

// ---------------------------------------------------------------------------
// PatchNCELoss B=8192 D=128 T=0.07 via mma.sync m16n8k16 fp16 (HMMA).
// loss[b] = 1/T + log(sum_k exp((S[b,k]-1)/T)) - pos[b]/T
// A pre-scaled by log2(e)/T; accumulators init at -log2(e)/T.
// Warp tile 64x32 split into two mi-halves; epilogue of each half is
// interleaved (4 ex2 per kk step) into the NEXT half's MMA loop, so MUFU
// work issues in the HMMA shadow without doubling accumulator registers.
// ---------------------------------------------------------------------------

#define BN  8192
#define BN2 8320              // 65 * 128
#define DD  128
#define KS  4                 // key splits
#define NC  16                // 128-key chunks per CTA (8192/128/KS)
#define GRID_X 65

#define INV_T    14.285714285714286f
#define SCALE_L2 20.609929155556620f   /* log2(e)/T */

static __device__ __half g_Ap[BN2 * DD];   // fragment-permuted A * SCALE_L2
static __device__ __half g_Bv[BN * DD];    // fragment-permuted v_n keys
static __device__ __half g_Bi[BN * DD];    // fragment-permuted i_n keys
static __device__ float  g_posT[BN2];
static __device__ int    g_orig[BN2];
static __device__ int    g_cnt[2];
static __device__ float  g_partial[KS * BN2];

// smem: A 32KB | B0 32KB | B1 32KB
#define SMEM_TOT 98304

// ---------------------------------------------------------------------------
__device__ __forceinline__ float ex2f(float x) {
    float r; asm("ex2.approx.f32 %0,%1;" : "=f"(r) : "f"(x)); return r;
}
__device__ __forceinline__ uint32_t s2u(const void* p) {
    uint32_t a;
    asm("{ .reg .u64 t; cvta.to.shared.u64 t, %1; cvt.u32.u64 %0, t; }"
        : "=r"(a) : "l"(p));
    return a;
}
#define CPA16(dst, src) \
    asm volatile("cp.async.cg.shared.global [%0], [%1], 16;" :: "r"(dst), "l"(src))
#define CP_COMMIT() asm volatile("cp.async.commit_group;" ::: "memory")
#define CP_WAIT1()  asm volatile("cp.async.wait_group 1;" ::: "memory")

#define LDS128(r, a) \
    asm volatile("ld.shared.v4.b32 {%0,%1,%2,%3}, [%4];" \
        : "=r"((r)[0]), "=r"((r)[1]), "=r"((r)[2]), "=r"((r)[3]) : "r"(a))
#define LDS64(r, a) \
    asm volatile("ld.shared.v2.b32 {%0,%1}, [%2];" \
        : "=r"((r)[0]), "=r"((r)[1]) : "r"(a))

__device__ __forceinline__ void mma16816(float* c, const uint32_t* a,
                                         const uint32_t* b) {
    asm volatile(
        "mma.sync.aligned.m16n8k16.row.col.f32.f16.f16.f32 "
        "{%0,%1,%2,%3}, {%4,%5,%6,%7}, {%8,%9}, {%0,%1,%2,%3};"
        : "+f"(c[0]), "+f"(c[1]), "+f"(c[2]), "+f"(c[3])
        : "r"(a[0]), "r"(a[1]), "r"(a[2]), "r"(a[3]), "r"(b[0]), "r"(b[1]));
}

// fragment-permuted half index helpers
__device__ __forceinline__ int a_perm_idx(int s, int t) {
    int mb = s >> 4, q = s & 15, g = q & 7, hi = q >> 3;
    int kk = t >> 4, tc = t & 15, kh = tc >> 3, t4 = (tc >> 1) & 3, h = tc & 1;
    int lane = g * 4 + t4, r = hi + 2 * kh;
    return (((mb * 8 + kk) * 32 + lane) << 3) + r * 2 + h;
}
__device__ __forceinline__ int b_perm_idx(int b, int t) {
    int nb = b >> 3, g = b & 7;
    int kk = t >> 4, tc = t & 15, kh = tc >> 3, t4 = (tc >> 1) & 3, h = tc & 1;
    int lane = g * 4 + t4;
    return (((nb * 8 + kk) * 32 + lane) << 2) + kh * 2 + h;
}

// ---------------------------------------------------------------------------
__global__ void init_kernel() {
    if (threadIdx.x == 0) { g_cnt[0] = 0; g_cnt[1] = 0; }
}

__global__ void prep_kernel(const float* __restrict__ fv,
                            const float* __restrict__ fi,
                            const float* __restrict__ v,
                            const float* __restrict__ vi) {
    int b = blockIdx.x;
    int t = threadIdx.x;
    float xfv = fv[b * DD + t];
    float xfi = fi[b * DD + t];
    float xv  = v [b * DD + t];
    float xi  = vi[b * DD + t];

    float s[6];
    s[0] = xfv * xfv; s[1] = xfi * xfi; s[2] = xv * xv;
    s[3] = xi * xi;   s[4] = xfv * xv;  s[5] = xfi * xi;
#pragma unroll
    for (int off = 16; off; off >>= 1)
#pragma unroll
        for (int k = 0; k < 6; ++k)
            s[k] += __shfl_xor_sync(0xffffffffu, s[k], off);

    __shared__ float sh[4][6];
    __shared__ float bc[3];
    __shared__ int   bsl[2];
    int w = t >> 5, lane = t & 31;
    if (lane == 0)
#pragma unroll
        for (int k = 0; k < 6; ++k) sh[w][k] = s[k];
    __syncthreads();

    if (t == 0) {
        float tot[6];
#pragma unroll
        for (int k = 0; k < 6; ++k)
            tot[k] = sh[0][k] + sh[1][k] + sh[2][k] + sh[3][k];
        float inv_fv = 1.f / fmaxf(sqrtf(tot[0]), 1e-12f);
        float inv_fi = 1.f / fmaxf(sqrtf(tot[1]), 1e-12f);
        float inv_v  = 1.f / fmaxf(sqrtf(tot[2]), 1e-12f);
        float inv_i  = 1.f / fmaxf(sqrtf(tot[3]), 1e-12f);
        float pos_v = tot[4] * inv_fv * inv_v;
        float pos_i = tot[5] * inv_fi * inv_i;
        bool use_v = (pos_v >= pos_i);
        int slot = use_v ? atomicAdd(&g_cnt[0], 1)
                         : (BN2 - 1 - atomicAdd(&g_cnt[1], 1));
        g_orig[slot] = b;
        g_posT[slot] = (use_v ? pos_v : pos_i) * INV_T;
        bc[0] = inv_v; bc[1] = inv_i; bc[2] = use_v ? inv_fv : inv_fi;
        bsl[0] = slot; bsl[1] = use_v ? 1 : 0;
    }
    __syncthreads();

    g_Bv[b_perm_idx(b, t)] = __float2half_rn(xv * bc[0]);
    g_Bi[b_perm_idx(b, t)] = __float2half_rn(xi * bc[1]);
    g_Ap[a_perm_idx(bsl[0], t)] =
        __float2half_rn((bsl[1] ? xfv : xfi) * bc[2] * SCALE_L2);
}

__global__ void zero_pad_kernel() {
    int row = g_cnt[0] + blockIdx.x;
    int t = threadIdx.x;
    g_Ap[a_perm_idx(row, t)] = __float2half_rn(0.f);
    if (t == 0) g_orig[row] = -1;
}

// ---------------------------------------------------------------------------
// one half-phase: 64 MMAs for rows [mi0*16, mi0*32+..], with optional
// interleaved epilogue of the OTHER half's finished accumulators.
// cN = accumulators written (8 tiles x 4), cE = bank consumed by epilogue.
// rbase: rsum index base for cE's rows (0 for halfA, 4 for halfB).
template <bool EPI>
__device__ __forceinline__ void half_phase(uint32_t aoffH, uint32_t sB,
                                           float (&cN)[8][4],
                                           float (&cE)[8][4],
                                           float (&rsum)[8], int rbase) {
#pragma unroll
    for (int tI = 0; tI < 8; ++tI)
#pragma unroll
        for (int x = 0; x < 4; ++x) cN[tI][x] = -SCALE_L2;

#pragma unroll
    for (int kk = 0; kk < 8; ++kk) {
        uint32_t a0[4], a1[4], b[4][2];
        LDS128(a0, aoffH + (uint32_t)(kk * 512));
        LDS128(a1, aoffH + (uint32_t)(4096 + kk * 512));
#pragma unroll
        for (int ni = 0; ni < 4; ++ni)
            LDS64(b[ni], sB + (uint32_t)(ni * 2048 + kk * 256));
#pragma unroll
        for (int ni = 0; ni < 4; ++ni)
            mma16816(cN[ni], a0, b[ni]);
#pragma unroll
        for (int ni = 0; ni < 4; ++ni)
            mma16816(cN[4 + ni], a1, b[ni]);

        if (EPI) {
            // consume one finished tile of the other bank per kk step
            float* e = cE[kk];
            int r = rbase + (kk >> 2) * 2;
            rsum[r]     += ex2f(e[0]) + ex2f(e[1]);
            rsum[r + 1] += ex2f(e[2]) + ex2f(e[3]);
        }
    }
}

__global__ __launch_bounds__(256, 2) void gemm_lse_kernel() {
    extern __shared__ __align__(16) unsigned char sm[];
    __shared__ float red[128][4];

    const uint32_t smA  = s2u(sm);
    const uint32_t smB0 = smA + 32768u;
    const uint32_t smB1 = smA + 65536u;

    const int tid  = threadIdx.x;
    const int lane = tid & 31;
    const int wid  = tid >> 5;
    const int wm = wid >> 2;          // 0..1  (64-row block)
    const int wn = wid & 3;           // 0..3  (32-key block)

    const int c0 = g_cnt[0];
    const int bx = blockIdx.x, ks = blockIdx.y;
    const int grp = (bx > (c0 >> 7)) ? 1 : 0;
    const int row0 = bx << 7;
    const char* __restrict__ Kb = (const char*)(grp ? g_Bi : g_Bv);

    // A tile + B chunk 0
    {
        const char* Asrc = (const char*)g_Ap + (size_t)row0 * 256;
#pragma unroll
        for (int q = 0; q < 8; ++q) {
            int i = (tid + q * 256) * 16;
            CPA16(smA + (uint32_t)i, Asrc + i);
        }
        const char* Bsrc = Kb + (size_t)ks * 32768;
#pragma unroll
        for (int q = 0; q < 8; ++q) {
            int i = (tid + q * 256) * 16;
            CPA16(smB0 + (uint32_t)i, Bsrc + i);
        }
        CP_COMMIT();
    }

    float cA[8][4], cB[8][4];
    float rsum[8];
#pragma unroll
    for (int i = 0; i < 8; ++i) rsum[i] = 0.f;

    const uint32_t aoff = smA + (uint32_t)(wm * 16384 + lane * 16);
    const uint32_t boff = (uint32_t)(wn * 8192 + lane * 8);

#pragma unroll 1
    for (int ci = 0; ci < NC; ++ci) {
        if (ci + 1 < NC) {
            const char* Bsrc = Kb + (size_t)(ks + (ci + 1) * KS) * 32768;
            uint32_t dst = ((ci + 1) & 1) ? smB1 : smB0;
#pragma unroll
            for (int q = 0; q < 8; ++q) {
                int i = (tid + q * 256) * 16;
                CPA16(dst + (uint32_t)i, Bsrc + i);
            }
            CP_COMMIT();
            CP_WAIT1();
        } else {
            asm volatile("cp.async.wait_group 0;" ::: "memory");
        }
        __syncthreads();

        const uint32_t sB = ((ci & 1) ? smB1 : smB0) + boff;

        // phase 1: halfA MMAs (+ epilogue of prev chunk's halfB)
        if (ci == 0) half_phase<false>(aoff, sB, cA, cB, rsum, 4);
        else         half_phase<true >(aoff, sB, cA, cB, rsum, 4);
        // phase 2: halfB MMAs + epilogue of this chunk's halfA
        half_phase<true>(aoff + 8192u, sB, cB, cA, rsum, 0);

        __syncthreads();
    }

    // drain: epilogue of final chunk's halfB
#pragma unroll
    for (int tI = 0; tI < 8; ++tI) {
        int r = 4 + (tI >> 2) * 2;
        rsum[r]     += ex2f(cB[tI][0]) + ex2f(cB[tI][1]);
        rsum[r + 1] += ex2f(cB[tI][2]) + ex2f(cB[tI][3]);
    }

    // reduce across the 4 col-lanes of each row
#pragma unroll
    for (int mi = 0; mi < 4; ++mi)
#pragma unroll
        for (int h = 0; h < 2; ++h) {
            float val = rsum[mi * 2 + h];
            val += __shfl_xor_sync(0xffffffffu, val, 1);
            val += __shfl_xor_sync(0xffffffffu, val, 2);
            if ((lane & 3) == 0)
                red[wm * 64 + mi * 16 + h * 8 + (lane >> 2)][wn] = val;
        }
    __syncthreads();

    if (tid < 128) {
        int slot = row0 + tid;
        float sum = red[tid][0] + red[tid][1] + red[tid][2] + red[tid][3];
        g_partial[ks * BN2 + slot] = sum;
    }
}

// ---------------------------------------------------------------------------
__global__ void finalize_kernel(float* __restrict__ out) {
    int s = blockIdx.x * 256 + threadIdx.x;
    if (s < BN2) {
        int o = g_orig[s];
        if (o >= 0) {
            float sum = g_partial[s] + g_partial[BN2 + s] +
                        g_partial[2 * BN2 + s] + g_partial[3 * BN2 + s];
            out[o] = INV_T + logf(sum) - g_posT[s];
        }
    }
}

// ---------------------------------------------------------------------------
extern "C" void kernel_launch(void* const* d_in, const int* in_sizes, int n_in,
                              void* d_out, int out_size) {
    (void)in_sizes; (void)n_in; (void)out_size;
    const float* fv = (const float*)d_in[0];
    const float* fi = (const float*)d_in[1];
    const float* v  = (const float*)d_in[2];
    const float* vi = (const float*)d_in[3];
    float* out = (float*)d_out;

    cudaFuncSetAttribute(gemm_lse_kernel,
                         cudaFuncAttributeMaxDynamicSharedMemorySize, SMEM_TOT);

    init_kernel<<<1, 32>>>();
    prep_kernel<<<BN, 128>>>(fv, fi, v, vi);
    zero_pad_kernel<<<128, 128>>>();
    gemm_lse_kernel<<<dim3(GRID_X, KS), 256, SMEM_TOT>>>();
    finalize_kernel<<<(BN2 + 255) / 256, 256>>>(out);
}